// round 2
// baseline (speedup 1.0000x reference)
#include <cuda_runtime.h>

// Problem geometry
#define S      160
#define NB     4
#define SLICE  (S * S)              // 25600
#define S3     (S * S * S)          // 4,096,000
#define NVOX   (NB * S3)            // 16,384,000
#define SSIM_C1 0.0001f             // 0.01^2
#define SSIM_C2 0.0009f             // 0.03^2

// Scratch: 5 channels (x, y, x^2, y^2, xy). Layout [c][n][d][h][w].
__device__ float g_bufA[5 * NVOX];
__device__ float g_bufB[5 * NVOX];
__device__ double g_sum;

// 11-tap Gaussian, sigma=1.5, normalized.
#define GW_INIT { 0.00102838f, 0.00759875f, 0.03600078f, 0.10936070f, \
                  0.21300554f, 0.26601172f, 0.21300554f, 0.10936070f, \
                  0.03600078f, 0.00759875f, 0.00102838f }

// ---------------------------------------------------------------------------
// K0: zero the accumulator (every replay)
// ---------------------------------------------------------------------------
__global__ void k0_init() { g_sum = 0.0; }

// ---------------------------------------------------------------------------
// K1: products + conv along W. One block per (n,d,h) line, one thread per w.
// Direct windowed sums from shared memory with explicit bounds checks.
// ---------------------------------------------------------------------------
__global__ __launch_bounds__(S) void k1_prod_wconv(
    const float* __restrict__ x, const float* __restrict__ y)
{
    const float GW[11] = GW_INIT;
    __shared__ float xs[S];
    __shared__ float ys[S];

    const int h = blockIdx.x;
    const int d = blockIdx.y;
    const int n = blockIdx.z;
    const int w = threadIdx.x;
    const size_t base = (size_t)n * S3 + (size_t)d * SLICE + (size_t)h * S;

    xs[w] = x[base + w];
    ys[w] = y[base + w];
    __syncthreads();

    float A = 0.f, B = 0.f, AA = 0.f, BB = 0.f, AB = 0.f;
    #pragma unroll
    for (int k = 0; k < 11; ++k) {
        const int ww = w - 5 + k;
        if (ww >= 0 && ww < S) {
            const float a = xs[ww];
            const float b = ys[ww];
            const float g = GW[k];
            A  += g * a;
            B  += g * b;
            AA += g * (a * a);
            BB += g * (b * b);
            AB += g * (a * b);
        }
    }

    const size_t o = base + w;
    g_bufA[               o] = A;
    g_bufA[(size_t)1*NVOX + o] = B;
    g_bufA[(size_t)2*NVOX + o] = AA;
    g_bufA[(size_t)3*NVOX + o] = BB;
    g_bufA[(size_t)4*NVOX + o] = AB;
}

// ---------------------------------------------------------------------------
// K2: conv along H. One thread per (c*NB+n, d, w) column; gather-form shift
// register: win[k] == in[o-5+k]. Each input loaded exactly once.
// ---------------------------------------------------------------------------
__global__ __launch_bounds__(S) void k2_hconv()
{
    const float GW[11] = GW_INIT;
    const int d  = blockIdx.x;
    const int cn = blockIdx.y;        // flat [c][n] index, 0..19
    const int w  = threadIdx.x;

    const float* __restrict__ src = g_bufA + (size_t)cn * S3 + (size_t)d * SLICE + w;
    float*       __restrict__ dst = g_bufB + (size_t)cn * S3 + (size_t)d * SLICE + w;

    float win[11];
    #pragma unroll
    for (int k = 0; k < 11; ++k)
        win[k] = (k >= 5) ? src[(size_t)(k - 5) * S] : 0.f;   // in[0..5]

    for (int ob = 0; ob < 165; ob += 11) {
        #pragma unroll
        for (int u = 0; u < 11; ++u) {
            const int o = ob + u;
            if (o < S) {
                float s = 0.f;
                #pragma unroll
                for (int k = 0; k < 11; ++k) s += GW[k] * win[k];
                dst[(size_t)o * S] = s;
            }
            #pragma unroll
            for (int k = 0; k < 10; ++k) win[k] = win[k + 1];
            const int nx = o + 6;
            win[10] = (nx < S) ? src[(size_t)nx * S] : 0.f;
        }
    }
}

// ---------------------------------------------------------------------------
// K3: conv along D for all 5 channels + fused SSIM + reduction.
// One thread per (n,h,w); 5 shift registers along d.
// ---------------------------------------------------------------------------
__global__ __launch_bounds__(S) void k3_dconv_ssim()
{
    const float GW[11] = GW_INIT;
    const int h = blockIdx.x;
    const int n = blockIdx.y;
    const int w = threadIdx.x;

    const size_t off = (size_t)n * S3 + (size_t)h * S + w;
    const float* __restrict__ p0 = g_bufB +                 off;
    const float* __restrict__ p1 = g_bufB + (size_t)1*NVOX + off;
    const float* __restrict__ p2 = g_bufB + (size_t)2*NVOX + off;
    const float* __restrict__ p3 = g_bufB + (size_t)3*NVOX + off;
    const float* __restrict__ p4 = g_bufB + (size_t)4*NVOX + off;

    float w0[11], w1[11], w2[11], w3[11], w4[11];
    #pragma unroll
    for (int k = 0; k < 11; ++k) {
        if (k >= 5) {
            const size_t ds = (size_t)(k - 5) * SLICE;
            w0[k] = p0[ds]; w1[k] = p1[ds]; w2[k] = p2[ds];
            w3[k] = p3[ds]; w4[k] = p4[ds];
        } else {
            w0[k] = 0.f; w1[k] = 0.f; w2[k] = 0.f; w3[k] = 0.f; w4[k] = 0.f;
        }
    }

    float lsum = 0.f;

    for (int ob = 0; ob < 165; ob += 11) {
        #pragma unroll
        for (int u = 0; u < 11; ++u) {
            const int o = ob + u;
            if (o < S) {
                float mu1 = 0.f, mu2 = 0.f, xx = 0.f, yy = 0.f, xy = 0.f;
                #pragma unroll
                for (int k = 0; k < 11; ++k) {
                    const float g = GW[k];
                    mu1 += g * w0[k]; mu2 += g * w1[k];
                    xx  += g * w2[k]; yy  += g * w3[k];
                    xy  += g * w4[k];
                }
                const float mu1sq = mu1 * mu1;
                const float mu2sq = mu2 * mu2;
                const float mu12  = mu1 * mu2;
                const float s1  = xx - mu1sq;
                const float s2  = yy - mu2sq;
                const float s12 = xy - mu12;
                const float num = (2.f * mu12 + SSIM_C1) * (2.f * s12 + SSIM_C2);
                const float den = (mu1sq + mu2sq + SSIM_C1) * (s1 + s2 + SSIM_C2);
                lsum += num / den;
            }
            #pragma unroll
            for (int k = 0; k < 10; ++k) {
                w0[k] = w0[k + 1]; w1[k] = w1[k + 1]; w2[k] = w2[k + 1];
                w3[k] = w3[k + 1]; w4[k] = w4[k + 1];
            }
            const int nx = o + 6;
            if (nx < S) {
                const size_t ds = (size_t)nx * SLICE;
                w0[10] = p0[ds]; w1[10] = p1[ds]; w2[10] = p2[ds];
                w3[10] = p3[ds]; w4[10] = p4[ds];
            } else {
                w0[10] = 0.f; w1[10] = 0.f; w2[10] = 0.f; w3[10] = 0.f; w4[10] = 0.f;
            }
        }
    }

    // Block reduction (160 threads = 5 warps)
    #pragma unroll
    for (int t = 16; t > 0; t >>= 1)
        lsum += __shfl_xor_sync(0xffffffffu, lsum, t);
    __shared__ float red[5];
    const int wid = w >> 5, lane = w & 31;
    if (lane == 0) red[wid] = lsum;
    __syncthreads();
    if (w == 0) {
        const float bs = red[0] + red[1] + red[2] + red[3] + red[4];
        atomicAdd(&g_sum, (double)bs);
    }
}

// ---------------------------------------------------------------------------
// K4: finalize scalar
// ---------------------------------------------------------------------------
__global__ void k4_finalize(float* __restrict__ out)
{
    out[0] = (float)(1.0 - g_sum / (double)NVOX);
}

// ---------------------------------------------------------------------------
extern "C" void kernel_launch(void* const* d_in, const int* in_sizes, int n_in,
                              void* d_out, int out_size)
{
    const float* img1 = (const float*)d_in[0];
    const float* img2 = (const float*)d_in[1];
    float* out = (float*)d_out;

    k0_init<<<1, 1>>>();
    k1_prod_wconv<<<dim3(S, S, NB), S>>>(img1, img2);
    k2_hconv<<<dim3(S, 5 * NB), S>>>();
    k3_dconv_ssim<<<dim3(S, NB), S>>>();
    k4_finalize<<<1, 1>>>(out);
}

// round 3
// speedup vs baseline: 1.5151x; 1.5151x over previous
#include <cuda_runtime.h>

// Problem geometry
#define S      160
#define NB     4
#define SLICE  (S * S)              // 25600
#define S3     (S * S * S)          // 4,096,000
#define NVOX   (NB * S3)            // 16,384,000
#define SSIM_C1 0.0001f             // 0.01^2
#define SSIM_C2 0.0009f             // 0.03^2

// H-tile for fused W+H kernel
#define TH     15
#define HROWS  (TH + 10)            // 25
#define NTILE  11                   // ceil(160/15)

// Scratch: 5 channels (mu1-pre, mu2-pre, xx, yy, xy) after W+H conv.
// Layout [c][n][d][h][w].
__device__ float g_bufB[5 * NVOX];
__device__ double g_sum;

// 11-tap Gaussian, sigma=1.5, normalized.
#define GW_INIT { 0.00102838f, 0.00759875f, 0.03600078f, 0.10936070f, \
                  0.21300554f, 0.26601172f, 0.21300554f, 0.10936070f, \
                  0.03600078f, 0.00759875f, 0.00102838f }

__global__ void k0_init() { g_sum = 0.0; }

// ---------------------------------------------------------------------------
// K12: fused products + W-conv + H-conv for one (n, d, h-tile).
// 256 threads. Channel-sequential through shared wbuf.
// W-stage: warp per row, lane owns 5 outputs (stride-5 windows, gcd(5,32)=1
//          => conflict-free smem access).
// H-stage: thread per w, register shift window down the 25 wbuf rows.
// ---------------------------------------------------------------------------
__global__ __launch_bounds__(256) void k12_wh(
    const float* __restrict__ x, const float* __restrict__ y)
{
    const float GW[11] = GW_INIT;
    __shared__ float xs[HROWS][S];
    __shared__ float ys[HROWS][S];
    __shared__ float wb[HROWS][S];

    const int ht = blockIdx.x;
    const int d  = blockIdx.y;
    const int n  = blockIdx.z;
    const int h0 = ht * TH;
    const int tid = threadIdx.x;
    const size_t sbase = (size_t)n * S3 + (size_t)d * SLICE;

    // Load 25 input rows (zero-padded at volume edges), coalesced.
    for (int i = tid; i < HROWS * S; i += 256) {
        const int r = i / S, w = i % S;
        const int hh = h0 - 5 + r;
        float a = 0.f, b = 0.f;
        if (hh >= 0 && hh < S) {
            const size_t g = sbase + (size_t)hh * S + w;
            a = x[g]; b = y[g];
        }
        xs[r][w] = a; ys[r][w] = b;
    }
    __syncthreads();

    const int wid  = tid >> 5;
    const int lane = tid & 31;
    const int w0   = lane * 5;      // 32 lanes x 5 = 160 outputs per row

    #pragma unroll
    for (int c = 0; c < 5; ++c) {
        // ---- W-stage: conv along w of product channel c, all 25 rows ----
        for (int r = wid; r < HROWS; r += 8) {
            float p[15];
            #pragma unroll
            for (int j = 0; j < 15; ++j) {
                const int ww = w0 - 5 + j;
                float a = 0.f, b = 0.f;
                if (ww >= 0 && ww < S) { a = xs[r][ww]; b = ys[r][ww]; }
                p[j] = (c == 0) ? a
                     : (c == 1) ? b
                     : (c == 2) ? a * a
                     : (c == 3) ? b * b
                     :            a * b;
            }
            #pragma unroll
            for (int o = 0; o < 5; ++o) {
                float s = 0.f;
                #pragma unroll
                for (int k = 0; k < 11; ++k) s += GW[k] * p[o + k];
                wb[r][w0 + o] = s;
            }
        }
        __syncthreads();

        // ---- H-stage: conv along h via register shift window ----
        if (tid < S) {
            float win[11];
            #pragma unroll
            for (int k = 0; k < 11; ++k) win[k] = wb[k][tid];

            float* __restrict__ dst =
                g_bufB + (size_t)c * NVOX + sbase + (size_t)h0 * S + tid;

            #pragma unroll
            for (int o = 0; o < TH; ++o) {
                if (h0 + o < S) {
                    float s = 0.f;
                    #pragma unroll
                    for (int k = 0; k < 11; ++k) s += GW[k] * win[k];
                    dst[(size_t)o * S] = s;
                }
                #pragma unroll
                for (int k = 0; k < 10; ++k) win[k] = win[k + 1];
                if (o + 11 < HROWS) win[10] = wb[o + 11][tid];
            }
        }
        __syncthreads();   // wb reused by next channel
    }
}

// ---------------------------------------------------------------------------
// K3: conv along D (segmented into 4) + fused SSIM + reduction.
// Block: (h, n, seg); thread per w; 40 outputs per thread along d.
// ---------------------------------------------------------------------------
__global__ __launch_bounds__(S) void k3_dconv_ssim()
{
    const float GW[11] = GW_INIT;
    const int h   = blockIdx.x;
    const int n   = blockIdx.y;
    const int seg = blockIdx.z;
    const int d0  = seg * 40;
    const int w   = threadIdx.x;

    const size_t off = (size_t)n * S3 + (size_t)h * S + w;
    const float* __restrict__ p0 = g_bufB +                 off;
    const float* __restrict__ p1 = g_bufB + (size_t)1*NVOX + off;
    const float* __restrict__ p2 = g_bufB + (size_t)2*NVOX + off;
    const float* __restrict__ p3 = g_bufB + (size_t)3*NVOX + off;
    const float* __restrict__ p4 = g_bufB + (size_t)4*NVOX + off;

    float w0[11], w1[11], w2[11], w3[11], w4[11];
    #pragma unroll
    for (int k = 0; k < 11; ++k) {
        const int dd = d0 - 5 + k;
        if (dd >= 0 && dd < S) {
            const size_t ds = (size_t)dd * SLICE;
            w0[k] = p0[ds]; w1[k] = p1[ds]; w2[k] = p2[ds];
            w3[k] = p3[ds]; w4[k] = p4[ds];
        } else {
            w0[k] = 0.f; w1[k] = 0.f; w2[k] = 0.f; w3[k] = 0.f; w4[k] = 0.f;
        }
    }

    float lsum = 0.f;

    for (int ob = 0; ob < 44; ob += 11) {
        #pragma unroll
        for (int u = 0; u < 11; ++u) {
            const int o = ob + u;          // local output index, 0..43
            if (o < 40) {
                float mu1 = 0.f, mu2 = 0.f, xx = 0.f, yy = 0.f, xy = 0.f;
                #pragma unroll
                for (int k = 0; k < 11; ++k) {
                    const float g = GW[k];
                    mu1 += g * w0[k]; mu2 += g * w1[k];
                    xx  += g * w2[k]; yy  += g * w3[k];
                    xy  += g * w4[k];
                }
                const float mu1sq = mu1 * mu1;
                const float mu2sq = mu2 * mu2;
                const float mu12  = mu1 * mu2;
                const float s1  = xx - mu1sq;
                const float s2  = yy - mu2sq;
                const float s12 = xy - mu12;
                const float num = (2.f * mu12 + SSIM_C1) * (2.f * s12 + SSIM_C2);
                const float den = (mu1sq + mu2sq + SSIM_C1) * (s1 + s2 + SSIM_C2);
                lsum += __fdividef(num, den);
            }
            #pragma unroll
            for (int k = 0; k < 10; ++k) {
                w0[k] = w0[k + 1]; w1[k] = w1[k + 1]; w2[k] = w2[k + 1];
                w3[k] = w3[k + 1]; w4[k] = w4[k + 1];
            }
            const int dd = d0 + o + 6;
            if (o < 39 && dd < S) {
                const size_t ds = (size_t)dd * SLICE;
                w0[10] = p0[ds]; w1[10] = p1[ds]; w2[10] = p2[ds];
                w3[10] = p3[ds]; w4[10] = p4[ds];
            } else {
                w0[10] = 0.f; w1[10] = 0.f; w2[10] = 0.f; w3[10] = 0.f; w4[10] = 0.f;
            }
        }
    }

    // Block reduction (160 threads = 5 warps)
    #pragma unroll
    for (int t = 16; t > 0; t >>= 1)
        lsum += __shfl_xor_sync(0xffffffffu, lsum, t);
    __shared__ float red[5];
    const int wid = w >> 5, lane = w & 31;
    if (lane == 0) red[wid] = lsum;
    __syncthreads();
    if (w == 0) {
        const float bs = red[0] + red[1] + red[2] + red[3] + red[4];
        atomicAdd(&g_sum, (double)bs);
    }
}

__global__ void k4_finalize(float* __restrict__ out)
{
    out[0] = (float)(1.0 - g_sum / (double)NVOX);
}

// ---------------------------------------------------------------------------
extern "C" void kernel_launch(void* const* d_in, const int* in_sizes, int n_in,
                              void* d_out, int out_size)
{
    const float* img1 = (const float*)d_in[0];
    const float* img2 = (const float*)d_in[1];
    float* out = (float*)d_out;

    k0_init<<<1, 1>>>();
    k12_wh<<<dim3(NTILE, S, NB), 256>>>(img1, img2);
    k3_dconv_ssim<<<dim3(S, NB, 4), S>>>();
    k4_finalize<<<1, 1>>>(out);
}